// round 3
// baseline (speedup 1.0000x reference)
#include <cuda_runtime.h>
#include <cuda_bf16.h>

#define NP 12000
#define NN 100

__global__ __launch_bounds__(256)
void pfn_kernel(const float* __restrict__ px, const float* __restrict__ py,
                const float* __restrict__ pz, const float* __restrict__ pi,
                const int*   __restrict__ nv,
                const float* __restrict__ xs, const float* __restrict__ ys,
                const float* __restrict__ mk,
                const float* __restrict__ W,  const float* __restrict__ gamma,
                const float* __restrict__ beta, const float* __restrict__ bnm,
                const float* __restrict__ bnv,
                float* __restrict__ out)
{
    const int p    = blockIdx.x;
    const int t    = threadIdx.x;
    const int lane = t & 31;        // = output channel u (0..31)
    const int warp = t >> 5;        // 8 warps, each handles points n = warp, warp+8, ...
    const int base = p * NN;

    // ---- per-channel params: fold BN scale into weights ----
    const float s = rsqrtf(bnv[lane] + 1e-3f) * gamma[lane];
    const float b = beta[lane] - bnm[lane] * s;
    float w[9];
    #pragma unroll
    for (int c = 0; c < 9; c++) w[c] = W[lane * 9 + c] * s;

    // ---- pillar mean: sum over ALL N points (reference semantics), / num_voxels ----
    __shared__ float red[3][8];
    float sx = 0.f, sy = 0.f, sz = 0.f;
    if (t < NN) { sx = px[base + t]; sy = py[base + t]; sz = pz[base + t]; }
    #pragma unroll
    for (int o = 16; o; o >>= 1) {
        sx += __shfl_down_sync(0xffffffffu, sx, o);
        sy += __shfl_down_sync(0xffffffffu, sy, o);
        sz += __shfl_down_sync(0xffffffffu, sz, o);
    }
    if (lane == 0) { red[0][warp] = sx; red[1][warp] = sy; red[2][warp] = sz; }
    __syncthreads();
    const float inv_nv = 1.0f / (float)nv[p];
    float mx = 0.f, my = 0.f, mz = 0.f;
    #pragma unroll
    for (int i = 0; i < 8; i++) { mx += red[0][i]; my += red[1][i]; mz += red[2][i]; }
    mx *= inv_nv; my *= inv_nv; mz *= inv_nv;

    // ---- main pass: features -> scaled matvec -> +bias -> relu; track channel max ----
    float vmax = -1e30f;
    for (int n = warp; n < NN; n += 8) {
        // warp-uniform loads: one 32B sector each
        const float x0 = px[base + n];
        const float y0 = py[base + n];
        const float z0 = pz[base + n];
        const float i0 = pi[base + n];
        const float xc = xs[base + n];
        const float yc = ys[base + n];
        const float m  = mk[base + n];

        float dot = x0 * w[0];
        dot = fmaf(y0,      w[1], dot);
        dot = fmaf(z0,      w[2], dot);
        dot = fmaf(i0,      w[3], dot);
        dot = fmaf(x0 - mx, w[4], dot);
        dot = fmaf(y0 - my, w[5], dot);
        dot = fmaf(z0 - mz, w[6], dot);
        dot = fmaf(x0 - xc, w[7], dot);
        dot = fmaf(y0 - yc, w[8], dot);

        // mask scales features pre-matmul; m in {0,1} so m*(f.W) is exact
        const float x = fmaxf(fmaf(m, dot, b), 0.0f);
        out[(size_t)(base + n) * 64 + lane] = x;   // coalesced 128B per warp
        vmax = fmaxf(vmax, x);
    }

    // ---- block max-reduce per channel ----
    __shared__ float smax[8][32];
    smax[warp][lane] = vmax;
    __syncthreads();
    float gm = smax[0][lane];
    #pragma unroll
    for (int i = 1; i < 8; i++) gm = fmaxf(gm, smax[i][lane]);

    // ---- broadcast pass: x_repeat into channels 32..63 ----
    for (int n = warp; n < NN; n += 8) {
        out[(size_t)(base + n) * 64 + 32 + lane] = gm;
    }
}

extern "C" void kernel_launch(void* const* d_in, const int* in_sizes, int n_in,
                              void* d_out, int out_size)
{
    const float* px = (const float*)d_in[0];
    const float* py = (const float*)d_in[1];
    const float* pz = (const float*)d_in[2];
    const float* pi = (const float*)d_in[3];
    const int*   nv = (const int*)  d_in[4];
    const float* xs = (const float*)d_in[5];
    const float* ys = (const float*)d_in[6];
    const float* mk = (const float*)d_in[7];
    const float* W  = (const float*)d_in[8];
    const float* ga = (const float*)d_in[9];
    const float* be = (const float*)d_in[10];
    const float* bm = (const float*)d_in[11];
    const float* bv = (const float*)d_in[12];
    float* out = (float*)d_out;

    pfn_kernel<<<NP, 256>>>(px, py, pz, pi, nv, xs, ys, mk, W, ga, be, bm, bv, out);
}

// round 4
// speedup vs baseline: 1.2755x; 1.2755x over previous
#include <cuda_runtime.h>
#include <cuda_bf16.h>

#define NP 12000
#define NN 100

__global__ __launch_bounds__(256)
void pfn_kernel(const float* __restrict__ px, const float* __restrict__ py,
                const float* __restrict__ pz, const float* __restrict__ pi,
                const int*   __restrict__ nv,
                const float* __restrict__ xs, const float* __restrict__ ys,
                const float* __restrict__ mk,
                const float* __restrict__ W,  const float* __restrict__ gamma,
                const float* __restrict__ beta, const float* __restrict__ bnm,
                const float* __restrict__ bnv,
                float* __restrict__ out)
{
    __shared__ float feat[NN][8];   // x, y, z, i, xsub, ysub, mask, pad
    __shared__ float means[3];
    __shared__ float smax[8][32];

    const int t    = threadIdx.x;
    const int lane = t & 31;
    const int warp = t >> 5;
    const int p    = blockIdx.x;
    const int base = p * NN;

    // ---- stage pillar inputs into shared (warp w loads array w, coalesced) ----
    {
        const float* src = 0;
        switch (warp) {
            case 0: src = px; break;
            case 1: src = py; break;
            case 2: src = pz; break;
            case 3: src = pi; break;
            case 4: src = xs; break;
            case 5: src = ys; break;
            case 6: src = mk; break;
            default: break;
        }
        if (src)
            for (int n = lane; n < NN; n += 32) feat[n][warp] = src[base + n];
    }

    // ---- per-thread folded weights: 4 channels each ----
    const int g   = lane >> 3;      // point subgroup 0..3 (4 points per warp per iter)
    const int cg  = lane & 7;       // channel group 0..7
    const int ch0 = cg * 4;         // first of 4 channels
    float w[9][4], b[4];
    #pragma unroll
    for (int j = 0; j < 4; j++) {
        const int u = ch0 + j;
        const float s = rsqrtf(bnv[u] + 1e-3f) * gamma[u];
        b[j] = beta[u] - bnm[u] * s;
        #pragma unroll
        for (int c = 0; c < 9; c++) w[c][j] = W[u * 9 + c] * s;
    }
    __syncthreads();

    // ---- pillar mean: warps 0..2 reduce x/y/z sums from shared ----
    if (warp < 3) {
        float s = 0.f;
        for (int n = lane; n < NN; n += 32) s += feat[n][warp];
        #pragma unroll
        for (int o = 16; o; o >>= 1) s += __shfl_down_sync(0xffffffffu, s, o);
        if (lane == 0) means[warp] = s;
    }
    __syncthreads();

    const float inv = 1.0f / (float)nv[p];
    const float mx = means[0] * inv, my = means[1] * inv, mz = means[2] * inv;

    // ---- main loop: 4 points per warp per iter, 4 channels per thread ----
    float vmax[4] = {-1e30f, -1e30f, -1e30f, -1e30f};
    #pragma unroll
    for (int it = 0; it < 4; it++) {
        const int n = it * 32 + warp * 4 + g;
        if (n < NN) {
            const float4 a  = *(const float4*)&feat[n][0];   // x y z i
            const float4 c4 = *(const float4*)&feat[n][4];   // xsub ysub mask pad
            const float f4 = a.x - mx, f5 = a.y - my, f6 = a.z - mz;
            const float f7 = a.x - c4.x, f8 = a.y - c4.y;
            const float m  = c4.z;
            float4 r;
            float* rp = &r.x;
            #pragma unroll
            for (int j = 0; j < 4; j++) {
                float d = a.x * w[0][j];
                d = fmaf(a.y, w[1][j], d);
                d = fmaf(a.z, w[2][j], d);
                d = fmaf(a.w, w[3][j], d);
                d = fmaf(f4,  w[4][j], d);
                d = fmaf(f5,  w[5][j], d);
                d = fmaf(f6,  w[6][j], d);
                d = fmaf(f7,  w[7][j], d);
                d = fmaf(f8,  w[8][j], d);
                const float x = fmaxf(fmaf(m, d, b[j]), 0.0f);
                rp[j] = x;
                vmax[j] = fmaxf(vmax[j], x);
            }
            *(float4*)&out[(size_t)(base + n) * 64 + ch0] = r;   // STG.128
        }
    }

    // ---- channel max: reduce across point-subgroups (lanes ±8, ±16), then warps ----
    #pragma unroll
    for (int j = 0; j < 4; j++) {
        vmax[j] = fmaxf(vmax[j], __shfl_xor_sync(0xffffffffu, vmax[j], 8));
        vmax[j] = fmaxf(vmax[j], __shfl_xor_sync(0xffffffffu, vmax[j], 16));
    }
    if (g == 0) {
        #pragma unroll
        for (int j = 0; j < 4; j++) smax[warp][ch0 + j] = vmax[j];
    }
    __syncthreads();

    float4 g4;
    {
        float gm[4];
        #pragma unroll
        for (int j = 0; j < 4; j++) {
            float v = smax[0][ch0 + j];
            #pragma unroll
            for (int i = 1; i < 8; i++) v = fmaxf(v, smax[i][ch0 + j]);
            gm[j] = v;
        }
        g4 = make_float4(gm[0], gm[1], gm[2], gm[3]);
    }

    // ---- broadcast pass: channels 32..63 = per-channel pillar max ----
    #pragma unroll
    for (int it = 0; it < 4; it++) {
        const int n = it * 32 + warp * 4 + g;
        if (n < NN)
            *(float4*)&out[(size_t)(base + n) * 64 + 32 + ch0] = g4;  // STG.128
    }
}

extern "C" void kernel_launch(void* const* d_in, const int* in_sizes, int n_in,
                              void* d_out, int out_size)
{
    const float* px = (const float*)d_in[0];
    const float* py = (const float*)d_in[1];
    const float* pz = (const float*)d_in[2];
    const float* pi = (const float*)d_in[3];
    const int*   nv = (const int*)  d_in[4];
    const float* xs = (const float*)d_in[5];
    const float* ys = (const float*)d_in[6];
    const float* mk = (const float*)d_in[7];
    const float* W  = (const float*)d_in[8];
    const float* ga = (const float*)d_in[9];
    const float* be = (const float*)d_in[10];
    const float* bm = (const float*)d_in[11];
    const float* bv = (const float*)d_in[12];
    float* out = (float*)d_out;

    pfn_kernel<<<NP, 256>>>(px, py, pz, pi, nv, xs, ys, mk, W, ga, be, bm, bv, out);
}

// round 5
// speedup vs baseline: 2.0828x; 1.6330x over previous
#include <cuda_runtime.h>
#include <cuda_bf16.h>

#define NP 12000
#define NN 100

__global__ __launch_bounds__(256)
void pfn_kernel(const float* __restrict__ px, const float* __restrict__ py,
                const float* __restrict__ pz, const float* __restrict__ pi,
                const int*   __restrict__ nv,
                const float* __restrict__ xs, const float* __restrict__ ys,
                const float* __restrict__ mk,
                const float* __restrict__ W,  const float* __restrict__ gamma,
                const float* __restrict__ beta, const float* __restrict__ bnm,
                const float* __restrict__ bnv,
                float* __restrict__ out)
{
    __shared__ float feat[NN][8];   // x, y, z, i, xsub, ysub, mask, pad
    __shared__ float means[3];
    __shared__ float smax[8][32];

    const int t    = threadIdx.x;
    const int lane = t & 31;
    const int warp = t >> 5;
    const int p    = blockIdx.x;
    const int base = p * NN;

    // ---- stage pillar inputs into shared (warp w loads array w, coalesced) ----
    {
        const float* src = 0;
        switch (warp) {
            case 0: src = px; break;
            case 1: src = py; break;
            case 2: src = pz; break;
            case 3: src = pi; break;
            case 4: src = xs; break;
            case 5: src = ys; break;
            case 6: src = mk; break;
            default: break;
        }
        if (src)
            for (int n = lane; n < NN; n += 32) feat[n][warp] = src[base + n];
    }

    // ---- 2 channels per thread: half-warp covers 32 channels of one point ----
    const int pt2 = lane >> 4;       // 0..1 : which of 2 points this warp-iter
    const int ch0 = (lane & 15) * 2; // first of 2 channels
    float w[9][2], b[2];
    #pragma unroll
    for (int j = 0; j < 2; j++) {
        const int u = ch0 + j;
        const float s = rsqrtf(bnv[u] + 1e-3f) * gamma[u];
        b[j] = beta[u] - bnm[u] * s;
        #pragma unroll
        for (int c = 0; c < 9; c++) w[c][j] = W[u * 9 + c] * s;
    }
    __syncthreads();

    // ---- pillar mean: warps 0..2 reduce x/y/z sums from shared ----
    if (warp < 3) {
        float s = 0.f;
        for (int n = lane; n < NN; n += 32) s += feat[n][warp];
        #pragma unroll
        for (int o = 16; o; o >>= 1) s += __shfl_down_sync(0xffffffffu, s, o);
        if (lane == 0) means[warp] = s;
    }
    __syncthreads();

    const float inv = 1.0f / (float)nv[p];
    const float mx = means[0] * inv, my = means[1] * inv, mz = means[2] * inv;

    float* const op = out + base * 64 + ch0;

    // ---- main loop: 2 points per warp per iter (16 per block-iter), 7 iters ----
    float vmax0 = -1e30f, vmax1 = -1e30f;
    #pragma unroll
    for (int it = 0; it < 7; it++) {
        const int n = it * 16 + warp * 2 + pt2;
        if (n < NN) {
            const float4 a  = *(const float4*)&feat[n][0];   // x y z i
            const float4 c4 = *(const float4*)&feat[n][4];   // xsub ysub mask pad
            const float f4 = a.x - mx, f5 = a.y - my, f6 = a.z - mz;
            const float f7 = a.x - c4.x, f8 = a.y - c4.y;
            const float m  = c4.z;
            float2 r;
            #pragma unroll
            for (int j = 0; j < 2; j++) {
                float d = a.x * w[0][j];
                d = fmaf(a.y, w[1][j], d);
                d = fmaf(a.z, w[2][j], d);
                d = fmaf(a.w, w[3][j], d);
                d = fmaf(f4,  w[4][j], d);
                d = fmaf(f5,  w[5][j], d);
                d = fmaf(f6,  w[6][j], d);
                d = fmaf(f7,  w[7][j], d);
                d = fmaf(f8,  w[8][j], d);
                const float x = fmaxf(fmaf(m, d, b[j]), 0.0f);
                if (j == 0) { r.x = x; vmax0 = fmaxf(vmax0, x); }
                else        { r.y = x; vmax1 = fmaxf(vmax1, x); }
            }
            __stcs((float2*)(op + n * 64), r);   // 128B contiguous per half-warp
        }
    }

    // ---- channel max: reduce across the 2 point-subgroups, then across warps ----
    vmax0 = fmaxf(vmax0, __shfl_xor_sync(0xffffffffu, vmax0, 16));
    vmax1 = fmaxf(vmax1, __shfl_xor_sync(0xffffffffu, vmax1, 16));
    if (pt2 == 0) {
        smax[warp][ch0]     = vmax0;
        smax[warp][ch0 + 1] = vmax1;
    }
    __syncthreads();

    float gm0 = smax[0][ch0], gm1 = smax[0][ch0 + 1];
    #pragma unroll
    for (int i = 1; i < 8; i++) {
        gm0 = fmaxf(gm0, smax[i][ch0]);
        gm1 = fmaxf(gm1, smax[i][ch0 + 1]);
    }
    const float2 g2 = make_float2(gm0, gm1);

    // ---- broadcast pass: channels 32..63 = per-channel pillar max ----
    #pragma unroll
    for (int it = 0; it < 7; it++) {
        const int n = it * 16 + warp * 2 + pt2;
        if (n < NN)
            __stcs((float2*)(op + n * 64 + 32), g2);
    }
}

extern "C" void kernel_launch(void* const* d_in, const int* in_sizes, int n_in,
                              void* d_out, int out_size)
{
    const float* px = (const float*)d_in[0];
    const float* py = (const float*)d_in[1];
    const float* pz = (const float*)d_in[2];
    const float* pi = (const float*)d_in[3];
    const int*   nv = (const int*)  d_in[4];
    const float* xs = (const float*)d_in[5];
    const float* ys = (const float*)d_in[6];
    const float* mk = (const float*)d_in[7];
    const float* W  = (const float*)d_in[8];
    const float* ga = (const float*)d_in[9];
    const float* be = (const float*)d_in[10];
    const float* bm = (const float*)d_in[11];
    const float* bv = (const float*)d_in[12];
    float* out = (float*)d_out;

    pfn_kernel<<<NP, 256>>>(px, py, pz, pi, nv, xs, ys, mk, W, ga, be, bm, bv, out);
}

// round 6
// speedup vs baseline: 2.4490x; 1.1758x over previous
#include <cuda_runtime.h>
#include <cuda_bf16.h>

#define NP 12000
#define NN 100
#define GRID 740          // 148 SMs x 5 resident CTAs
#define FP 104            // padded SoA row length

__global__ __launch_bounds__(256)
void pfn_kernel(const float* __restrict__ px, const float* __restrict__ py,
                const float* __restrict__ pz, const float* __restrict__ pi,
                const int*   __restrict__ nv,
                const float* __restrict__ xs, const float* __restrict__ ys,
                const float* __restrict__ mk,
                const float* __restrict__ W,  const float* __restrict__ gamma,
                const float* __restrict__ beta, const float* __restrict__ bnm,
                const float* __restrict__ bnv,
                float* __restrict__ out)
{
    __shared__ float feat[2][7][FP];   // SoA: x,y,z,i,xsub,ysub,mask
    __shared__ float means[2][3];
    __shared__ float smax[2][8][32];

    const int t    = threadIdx.x;
    const int lane = t & 31;
    const int warp = t >> 5;

    // staging role: warp w owns input array w (fixed for block lifetime)
    const float* src = 0;
    switch (warp) {
        case 0: src = px; break;
        case 1: src = py; break;
        case 2: src = pz; break;
        case 3: src = pi; break;
        case 4: src = xs; break;
        case 5: src = ys; break;
        case 6: src = mk; break;
        default: break;
    }

    // ---- folded weights, once per block: 2 channels per thread ----
    const int pt2 = lane >> 4;        // which of 2 points per warp-iter
    const int ch0 = (lane & 15) * 2;  // first of 2 channels
    float w[9][2], b[2];
    #pragma unroll
    for (int j = 0; j < 2; j++) {
        const int u = ch0 + j;
        const float s = rsqrtf(bnv[u] + 1e-3f) * gamma[u];
        b[j] = beta[u] - bnm[u] * s;
        #pragma unroll
        for (int c = 0; c < 9; c++) w[c][j] = W[u * 9 + c] * s;
    }

    // ---- staging: coalesced STS (conflict-free), mean partials via shuffle ----
    auto stage = [&](int pp, int bb) {
        if (src) {
            const int bs = pp * NN;
            float s = 0.f;
            #pragma unroll
            for (int k = 0; k < 4; k++) {
                const int n = lane + 32 * k;
                if (n < NN) {
                    const float v = src[bs + n];
                    feat[bb][warp][n] = v;
                    if (warp < 3) s += v;
                }
            }
            if (warp < 3) {
                #pragma unroll
                for (int o = 16; o; o >>= 1) s += __shfl_down_sync(0xffffffffu, s, o);
                if (lane == 0) means[bb][warp] = s;
            }
        }
    };

    int p = blockIdx.x;
    int buf = 0;
    stage(p, 0);

    for (; p < NP; p += GRID) {
        __syncthreads();   // feat[buf] + means[buf] ready

        const float* fp = &feat[buf][0][0];
        const float inv = 1.0f / (float)nv[p];
        const float mx = means[buf][0] * inv;
        const float my = means[buf][1] * inv;
        const float mz = means[buf][2] * inv;

        float* const op = out + (size_t)p * (NN * 64) + ch0;

        // ---- main pass: 2 points per warp per iter, 2 channels per thread ----
        float vmax0 = -1e30f, vmax1 = -1e30f;
        #pragma unroll
        for (int it = 0; it < 7; it++) {
            const int n = it * 16 + warp * 2 + pt2;
            if (n < NN) {
                const float x0 = fp[0 * FP + n];
                const float y0 = fp[1 * FP + n];
                const float z0 = fp[2 * FP + n];
                const float i0 = fp[3 * FP + n];
                const float xc = fp[4 * FP + n];
                const float yc = fp[5 * FP + n];
                const float m  = fp[6 * FP + n];
                const float f4 = x0 - mx, f5 = y0 - my, f6 = z0 - mz;
                const float f7 = x0 - xc, f8 = y0 - yc;
                float2 r;
                #pragma unroll
                for (int j = 0; j < 2; j++) {
                    float d = x0 * w[0][j];
                    d = fmaf(y0, w[1][j], d);
                    d = fmaf(z0, w[2][j], d);
                    d = fmaf(i0, w[3][j], d);
                    d = fmaf(f4, w[4][j], d);
                    d = fmaf(f5, w[5][j], d);
                    d = fmaf(f6, w[6][j], d);
                    d = fmaf(f7, w[7][j], d);
                    d = fmaf(f8, w[8][j], d);
                    const float x = fmaxf(fmaf(m, d, b[j]), 0.0f);
                    if (j == 0) { r.x = x; vmax0 = fmaxf(vmax0, x); }
                    else        { r.y = x; vmax1 = fmaxf(vmax1, x); }
                }
                __stcs((float2*)(op + n * 64), r);   // 128B per half-warp
            }
        }

        // ---- channel max across the 2 point-subgroups, then across warps ----
        vmax0 = fmaxf(vmax0, __shfl_xor_sync(0xffffffffu, vmax0, 16));
        vmax1 = fmaxf(vmax1, __shfl_xor_sync(0xffffffffu, vmax1, 16));
        if (pt2 == 0) {
            smax[buf][warp][ch0]     = vmax0;
            smax[buf][warp][ch0 + 1] = vmax1;
        }
        __syncthreads();   // smax[buf] ready

        float gm0 = smax[buf][0][ch0], gm1 = smax[buf][0][ch0 + 1];
        #pragma unroll
        for (int i = 1; i < 8; i++) {
            gm0 = fmaxf(gm0, smax[buf][i][ch0]);
            gm1 = fmaxf(gm1, smax[buf][i][ch0 + 1]);
        }
        const float2 g2 = make_float2(gm0, gm1);

        // ---- prefetch/stage next pillar into the other buffer (overlaps stores) ----
        const int pn = p + GRID;
        if (pn < NP) stage(pn, buf ^ 1);

        // ---- broadcast pass: channels 32..63 = per-channel pillar max ----
        #pragma unroll
        for (int it = 0; it < 7; it++) {
            const int n = it * 16 + warp * 2 + pt2;
            if (n < NN)
                __stcs((float2*)(op + n * 64 + 32), g2);
        }

        buf ^= 1;
    }
}

extern "C" void kernel_launch(void* const* d_in, const int* in_sizes, int n_in,
                              void* d_out, int out_size)
{
    const float* px = (const float*)d_in[0];
    const float* py = (const float*)d_in[1];
    const float* pz = (const float*)d_in[2];
    const float* pi = (const float*)d_in[3];
    const int*   nv = (const int*)  d_in[4];
    const float* xs = (const float*)d_in[5];
    const float* ys = (const float*)d_in[6];
    const float* mk = (const float*)d_in[7];
    const float* W  = (const float*)d_in[8];
    const float* ga = (const float*)d_in[9];
    const float* be = (const float*)d_in[10];
    const float* bm = (const float*)d_in[11];
    const float* bv = (const float*)d_in[12];
    float* out = (float*)d_out;

    pfn_kernel<<<GRID, 256>>>(px, py, pz, pi, nv, xs, ys, mk, W, ga, be, bm, bv, out);
}

// round 9
// speedup vs baseline: 2.6020x; 1.0624x over previous
#include <cuda_runtime.h>
#include <cuda_bf16.h>

#define NP 12000
#define NN 100
#define GRID 592          // 148 SMs x 4 resident CTAs (64 regs) — one balanced wave
#define FP 104            // padded SoA row length

__global__ __launch_bounds__(256)
void pfn_kernel(const float* __restrict__ px, const float* __restrict__ py,
                const float* __restrict__ pz, const float* __restrict__ pi,
                const int*   __restrict__ nv,
                const float* __restrict__ xs, const float* __restrict__ ys,
                const float* __restrict__ mk,
                const float* __restrict__ W,  const float* __restrict__ gamma,
                const float* __restrict__ beta, const float* __restrict__ bnm,
                const float* __restrict__ bnv,
                float* __restrict__ out)
{
    __shared__ float feat[2][7][FP];   // SoA: x,y,z,i,xsub,ysub,mask
    __shared__ float means[2][3];
    __shared__ float smax[2][8][32];

    const int t    = threadIdx.x;
    const int lane = t & 31;
    const int warp = t >> 5;

    // staging role: warp w owns input array w (fixed for block lifetime)
    const float* src = 0;
    switch (warp) {
        case 0: src = px; break;
        case 1: src = py; break;
        case 2: src = pz; break;
        case 3: src = pi; break;
        case 4: src = xs; break;
        case 5: src = ys; break;
        case 6: src = mk; break;
        default: break;
    }

    // ---- folded weights, once per block: 2 channels per thread ----
    const int pt2 = lane >> 4;        // which of 2 points per warp-iter
    const int ch0 = (lane & 15) * 2;  // first of 2 channels
    float w[9][2], b[2];
    #pragma unroll
    for (int j = 0; j < 2; j++) {
        const int u = ch0 + j;
        const float s = rsqrtf(bnv[u] + 1e-3f) * gamma[u];
        b[j] = beta[u] - bnm[u] * s;
        #pragma unroll
        for (int c = 0; c < 9; c++) w[c][j] = W[u * 9 + c] * s;
    }

    // ---- staging: coalesced STS (conflict-free), mean partials via shuffle ----
    auto stage = [&](int pp, int bb) {
        if (src) {
            const int bs = pp * NN;
            float s = 0.f;
            #pragma unroll
            for (int k = 0; k < 4; k++) {
                const int n = lane + 32 * k;
                if (n < NN) {
                    const float v = __ldcs(src + bs + n);   // read-once: evict-first
                    feat[bb][warp][n] = v;
                    if (warp < 3) s += v;
                }
            }
            if (warp < 3) {
                #pragma unroll
                for (int o = 16; o; o >>= 1) s += __shfl_down_sync(0xffffffffu, s, o);
                if (lane == 0) means[bb][warp] = s;
            }
        }
    };

    int p = blockIdx.x;
    int buf = 0;
    stage(p, 0);
    int nvcur = nv[p];                 // prefetched before the barrier

    for (; p < NP; p += GRID) {
        __syncthreads();   // feat[buf] + means[buf] ready

        const float* fp = &feat[buf][0][0];
        const float inv = 1.0f / (float)nvcur;
        const float mx = means[buf][0] * inv;
        const float my = means[buf][1] * inv;
        const float mz = means[buf][2] * inv;

        float* const op = out + (size_t)p * (NN * 64) + ch0;

        // ---- main pass: 2 points per warp per iter, 2 channels per thread ----
        float vmax0 = -1e30f, vmax1 = -1e30f;
        #pragma unroll
        for (int it = 0; it < 7; it++) {
            const int n = it * 16 + warp * 2 + pt2;
            if (n < NN) {
                const float x0 = fp[0 * FP + n];
                const float y0 = fp[1 * FP + n];
                const float z0 = fp[2 * FP + n];
                const float i0 = fp[3 * FP + n];
                const float xc = fp[4 * FP + n];
                const float yc = fp[5 * FP + n];
                const float m  = fp[6 * FP + n];
                const float f4 = x0 - mx, f5 = y0 - my, f6 = z0 - mz;
                const float f7 = x0 - xc, f8 = y0 - yc;
                float2 r;
                #pragma unroll
                for (int j = 0; j < 2; j++) {
                    float d = x0 * w[0][j];
                    d = fmaf(y0, w[1][j], d);
                    d = fmaf(z0, w[2][j], d);
                    d = fmaf(i0, w[3][j], d);
                    d = fmaf(f4, w[4][j], d);
                    d = fmaf(f5, w[5][j], d);
                    d = fmaf(f6, w[6][j], d);
                    d = fmaf(f7, w[7][j], d);
                    d = fmaf(f8, w[8][j], d);
                    const float x = fmaxf(fmaf(m, d, b[j]), 0.0f);
                    if (j == 0) { r.x = x; vmax0 = fmaxf(vmax0, x); }
                    else        { r.y = x; vmax1 = fmaxf(vmax1, x); }
                }
                __stcs((float2*)(op + n * 64), r);   // 128B per half-warp
            }
        }

        // ---- channel max across the 2 point-subgroups, then across warps ----
        vmax0 = fmaxf(vmax0, __shfl_xor_sync(0xffffffffu, vmax0, 16));
        vmax1 = fmaxf(vmax1, __shfl_xor_sync(0xffffffffu, vmax1, 16));
        if (pt2 == 0) {
            smax[buf][warp][ch0]     = vmax0;
            smax[buf][warp][ch0 + 1] = vmax1;
        }
        __syncthreads();   // smax[buf] ready

        float gm0 = smax[buf][0][ch0], gm1 = smax[buf][0][ch0 + 1];
        #pragma unroll
        for (int i = 1; i < 8; i++) {
            gm0 = fmaxf(gm0, smax[buf][i][ch0]);
            gm1 = fmaxf(gm1, smax[buf][i][ch0 + 1]);
        }
        const float2 g2 = make_float2(gm0, gm1);

        // ---- prefetch/stage next pillar into the other buffer (overlaps stores) ----
        const int pn = p + GRID;
        if (pn < NP) {
            stage(pn, buf ^ 1);
            nvcur = nv[pn];
        }

        // ---- broadcast pass: channels 32..63 = per-channel pillar max ----
        #pragma unroll
        for (int it = 0; it < 7; it++) {
            const int n = it * 16 + warp * 2 + pt2;
            if (n < NN)
                __stcs((float2*)(op + n * 64 + 32), g2);
        }

        buf ^= 1;
    }
}

extern "C" void kernel_launch(void* const* d_in, const int* in_sizes, int n_in,
                              void* d_out, int out_size)
{
    const float* px = (const float*)d_in[0];
    const float* py = (const float*)d_in[1];
    const float* pz = (const float*)d_in[2];
    const float* pi = (const float*)d_in[3];
    const int*   nv = (const int*)  d_in[4];
    const float* xs = (const float*)d_in[5];
    const float* ys = (const float*)d_in[6];
    const float* mk = (const float*)d_in[7];
    const float* W  = (const float*)d_in[8];
    const float* ga = (const float*)d_in[9];
    const float* be = (const float*)d_in[10];
    const float* bm = (const float*)d_in[11];
    const float* bv = (const float*)d_in[12];
    float* out = (float*)d_out;

    pfn_kernel<<<GRID, 256>>>(px, py, pz, pi, nv, xs, ys, mk, W, ga, be, bm, bv, out);
}

// round 13
// speedup vs baseline: 2.7552x; 1.0589x over previous
#include <cuda_runtime.h>
#include <cuda_bf16.h>

#define NP 12000
#define NN 100
#define GRID 740          // 148 SMs x 5 resident CTAs
#define RW 12             // padded AoS row: x y z i | xs ys mk pad | pad4 (48B, 16B multiple)

__global__ __launch_bounds__(256, 5)
void pfn_kernel(const float* __restrict__ px, const float* __restrict__ py,
                const float* __restrict__ pz, const float* __restrict__ pi,
                const int*   __restrict__ nv,
                const float* __restrict__ xs, const float* __restrict__ ys,
                const float* __restrict__ mk,
                const float* __restrict__ W,  const float* __restrict__ gamma,
                const float* __restrict__ beta, const float* __restrict__ bnm,
                const float* __restrict__ bnv,
                float* __restrict__ out)
{
    __shared__ __align__(16) float feat[2][NN][RW];
    __shared__ float means[2][3];
    __shared__ float smax[2][8][32];
    __shared__ __align__(16) float gmax[32];

    const int t    = threadIdx.x;
    const int lane = t & 31;
    const int warp = t >> 5;

    // staging role: warp w owns input array w (warp 7 is the gmax-reducer)
    const float* src = 0;
    switch (warp) {
        case 0: src = px; break;
        case 1: src = py; break;
        case 2: src = pz; break;
        case 3: src = pi; break;
        case 4: src = xs; break;
        case 5: src = ys; break;
        case 6: src = mk; break;
        default: break;
    }

    // ---- folded weights: 2 channels per thread ----
    const int pt2 = lane >> 4;        // which of 2 points per warp-iter
    const int ch0 = (lane & 15) * 2;  // first of 2 channels
    const int nb  = warp * 2 + pt2;   // base point index (0..15)
    float w[9][2], b[2];
    #pragma unroll
    for (int j = 0; j < 2; j++) {
        const int u = ch0 + j;
        const float s = rsqrtf(bnv[u] + 1e-3f) * gamma[u];
        b[j] = beta[u] - bnm[u] * s;
        #pragma unroll
        for (int c = 0; c < 9; c++) w[c][j] = W[u * 9 + c] * s;
    }

    // ---- staging: AoS rows, mean partials via shuffle ----
    auto stage = [&](int pp, int bb) {
        if (src) {
            const int bs = pp * NN;
            float s = 0.f;
            #pragma unroll
            for (int k = 0; k < 4; k++) {
                const int n = lane + 32 * k;
                if (k < 3 || lane < NN - 96) {
                    const float v = __ldcs(src + bs + n);
                    feat[bb][n][warp] = v;
                    if (warp < 3) s += v;
                }
            }
            if (warp < 3) {
                #pragma unroll
                for (int o = 16; o; o >>= 1) s += __shfl_down_sync(0xffffffffu, s, o);
                if (lane == 0) means[bb][warp] = s;
            }
        }
    };

    int p = blockIdx.x;
    int buf = 0;
    stage(p, 0);
    int nvcur = nv[p];
    __syncthreads();   // initial feat[0] ready

    for (; p < NP; p += GRID) {
        const float* f = &feat[buf][nb][0];
        const float inv = 1.0f / (float)nvcur;
        const float mx = means[buf][0] * inv;
        const float my = means[buf][1] * inv;
        const float mz = means[buf][2] * inv;

        float* const outp = out + (size_t)p * (NN * 64);
        float* const op   = outp + nb * 64 + ch0;

        // ---- main pass: 2 LDS.128 per point, float2 stores ----
        float vmax0 = -1e30f, vmax1 = -1e30f;
        #pragma unroll
        for (int it = 0; it < 7; it++) {
            if (it < 6 || nb < NN - 96) {
                const float4 a  = *(const float4*)(f + it * (16 * RW));
                const float4 c4 = *(const float4*)(f + it * (16 * RW) + 4);
                const float f4 = a.x - mx, f5 = a.y - my, f6 = a.z - mz;
                const float f7 = a.x - c4.x, f8 = a.y - c4.y;
                const float m  = c4.z;
                float2 r;
                #pragma unroll
                for (int j = 0; j < 2; j++) {
                    float d = a.x * w[0][j];
                    d = fmaf(a.y, w[1][j], d);
                    d = fmaf(a.z, w[2][j], d);
                    d = fmaf(a.w, w[3][j], d);
                    d = fmaf(f4,  w[4][j], d);
                    d = fmaf(f5,  w[5][j], d);
                    d = fmaf(f6,  w[6][j], d);
                    d = fmaf(f7,  w[7][j], d);
                    d = fmaf(f8,  w[8][j], d);
                    const float x = fmaxf(fmaf(m, d, b[j]), 0.0f);
                    if (j == 0) { r.x = x; vmax0 = fmaxf(vmax0, x); }
                    else        { r.y = x; vmax1 = fmaxf(vmax1, x); }
                }
                __stcs((float2*)(op + it * (16 * 64)), r);   // 128B per half-warp
            }
        }

        // ---- channel max partials into smax ----
        vmax0 = fmaxf(vmax0, __shfl_xor_sync(0xffffffffu, vmax0, 16));
        vmax1 = fmaxf(vmax1, __shfl_xor_sync(0xffffffffu, vmax1, 16));
        if (pt2 == 0) {
            smax[buf][warp][ch0]     = vmax0;
            smax[buf][warp][ch0 + 1] = vmax1;
        }
        __syncthreads();   // smax[buf] complete; feat[buf] fully consumed

        // ---- warp 7 reduces gmax while warps 0-6 stage the next pillar ----
        const int pn = p + GRID;
        if (warp == 7) {
            float g = smax[buf][0][lane];
            #pragma unroll
            for (int i = 1; i < 8; i++) g = fmaxf(g, smax[buf][i][lane]);
            gmax[lane] = g;
        } else if (pn < NP) {
            stage(pn, buf ^ 1);
        }
        int nvnext = nvcur;
        if (pn < NP) nvnext = nv[pn];
        __syncthreads();   // gmax ready + feat[buf^1] ready

        // ---- broadcast pass: STG.128, 8-lane groups write 128B rows ----
        {
            const int cg4 = (lane & 7) * 4;   // channel group (4 channels)
            const int pg  = lane >> 3;        // point-in-group (0..3)
            const float4 g4 = *(const float4*)&gmax[cg4];
            float* const bp = outp + (warp * 4 + pg) * 64 + 32 + cg4;
            #pragma unroll
            for (int it = 0; it < 4; it++) {
                if (it < 3 || warp * 4 + pg < NN - 96)
                    __stcs((float4*)(bp + it * (32 * 64)), g4);
            }
        }

        nvcur = nvnext;
        buf ^= 1;
    }
}

extern "C" void kernel_launch(void* const* d_in, const int* in_sizes, int n_in,
                              void* d_out, int out_size)
{
    const float* px = (const float*)d_in[0];
    const float* py = (const float*)d_in[1];
    const float* pz = (const float*)d_in[2];
    const float* pi = (const float*)d_in[3];
    const int*   nv = (const int*)  d_in[4];
    const float* xs = (const float*)d_in[5];
    const float* ys = (const float*)d_in[6];
    const float* mk = (const float*)d_in[7];
    const float* W  = (const float*)d_in[8];
    const float* ga = (const float*)d_in[9];
    const float* be = (const float*)d_in[10];
    const float* bm = (const float*)d_in[11];
    const float* bv = (const float*)d_in[12];
    float* out = (float*)d_out;

    pfn_kernel<<<GRID, 256>>>(px, py, pz, pi, nv, xs, ys, mk, W, ga, be, bm, bv, out);
}